// round 1
// baseline (speedup 1.0000x reference)
#include <cuda_runtime.h>

// YOLOv5 detect head: per-scale fused GEMM (1x1 conv) + sigmoid decode + scatter.
//
// y[b, n, s] = sum_c p[b, c, s] * w[n, c] + bias[n]     (n in [0,255), s spatial)
// n = a*85 + c ; decode per element:
//   c==0: (sig*2 + x - 0.5) * stride
//   c==1: (sig*2 + y - 0.5) * stride
//   c==2: (sig*2)^2 * anc[a].w
//   c==3: (sig*2)^2 * anc[a].h
//   else: sig
// out[b][a*S + s + row_off][c]  with out shape [bs, 25200, 85]

#define TM 64
#define TN 64
#define TK 16
#define NO 85
#define NTOT 255

__global__ __launch_bounds__(256)
void yolo_scale_kernel(const float* __restrict__ p,
                       const float* __restrict__ w,
                       const float* __restrict__ bias,
                       const float* __restrict__ anc,   // 6 floats for this scale
                       float* __restrict__ out,
                       int C, int S, int nx, float stride_,
                       int row_off, int M, int total_rows)
{
    __shared__ float As[TK][TM];
    __shared__ float Bs[TK][TN + 4];

    const int tid = threadIdx.x;
    const int m0  = blockIdx.x * TM;
    const int n0  = blockIdx.y * TN;

    // ---- A-load indexing (fixed across K loop) ----
    const int a_m = tid & 63;        // pixel within tile
    const int a_k = tid >> 6;        // 0..3 -> loads k = a_k + 4*kk
    const int gm  = m0 + a_m;
    long a_base = -1;
    if (gm < M) {
        int b  = gm / S;
        int s  = gm - b * S;
        a_base = (long)b * C * S + s;
    }

    // ---- B-load indexing ----
    const int b_k = tid & 15;
    const int b_n = tid >> 4;        // 0..15 -> loads n = b_n + 16*nn

    // ---- compute indexing ----
    const int tng = tid & 15;        // n group (x4)
    const int tmg = tid >> 4;        // m group (x4)

    float acc[4][4];
    #pragma unroll
    for (int i = 0; i < 4; i++)
        #pragma unroll
        for (int j = 0; j < 4; j++)
            acc[i][j] = 0.f;

    for (int k0 = 0; k0 < C; k0 += TK) {
        // load A tile: 64 m x 16 k
        #pragma unroll
        for (int kk = 0; kk < 4; kk++) {
            int k = a_k + kk * 4;
            float v = 0.f;
            if (a_base >= 0) v = p[a_base + (long)(k0 + k) * S];
            As[k][a_m] = v;
        }
        // load B tile: 16 k x 64 n   (w is [255, C] row-major)
        #pragma unroll
        for (int nn = 0; nn < 4; nn++) {
            int n  = b_n + nn * 16;
            int gn = n0 + n;
            float v = 0.f;
            if (gn < NTOT) v = w[(long)gn * C + k0 + b_k];
            Bs[b_k][n] = v;
        }
        __syncthreads();

        #pragma unroll
        for (int k = 0; k < TK; k++) {
            float ra[4], rb[4];
            const float4 va = *reinterpret_cast<const float4*>(&As[k][tmg * 4]);
            const float4 vb = *reinterpret_cast<const float4*>(&Bs[k][tng * 4]);
            ra[0] = va.x; ra[1] = va.y; ra[2] = va.z; ra[3] = va.w;
            rb[0] = vb.x; rb[1] = vb.y; rb[2] = vb.z; rb[3] = vb.w;
            #pragma unroll
            for (int i = 0; i < 4; i++)
                #pragma unroll
                for (int j = 0; j < 4; j++)
                    acc[i][j] = fmaf(ra[i], rb[j], acc[i][j]);
        }
        __syncthreads();
    }

    // ---- epilogue: bias + sigmoid + decode + scatter ----
    #pragma unroll
    for (int i = 0; i < 4; i++) {
        int m = m0 + tmg * 4 + i;
        if (m >= M) continue;
        int b  = m / S;
        int s  = m - b * S;
        int yy = s / nx;
        int xx = s - yy * nx;
        #pragma unroll
        for (int j = 0; j < 4; j++) {
            int n = n0 + tng * 4 + j;
            if (n >= NTOT) continue;
            float v  = acc[i][j] + bias[n];
            float sg = 1.f / (1.f + __expf(-v));
            int a = n / NO;
            int c = n - a * NO;
            float o;
            if (c == 0) {
                o = (sg * 2.f + (float)xx - 0.5f) * stride_;
            } else if (c == 1) {
                o = (sg * 2.f + (float)yy - 0.5f) * stride_;
            } else if (c == 2) {
                float t = sg * 2.f; o = t * t * anc[a * 2 + 0];
            } else if (c == 3) {
                float t = sg * 2.f; o = t * t * anc[a * 2 + 1];
            } else {
                o = sg;
            }
            long row = (long)row_off + (long)a * S + s;
            out[((long)b * total_rows + row) * (long)NO + c] = o;
        }
    }
}

extern "C" void kernel_launch(void* const* d_in, const int* in_sizes, int n_in,
                              void* d_out, int out_size)
{
    const float* p0 = (const float*)d_in[0];
    const float* p1 = (const float*)d_in[1];
    const float* p2 = (const float*)d_in[2];
    const float* w0 = (const float*)d_in[3];
    const float* b0 = (const float*)d_in[4];
    const float* w1 = (const float*)d_in[5];
    const float* b1 = (const float*)d_in[6];
    const float* w2 = (const float*)d_in[7];
    const float* b2 = (const float*)d_in[8];
    const float* anchors = (const float*)d_in[9];
    float* out = (float*)d_out;

    const int bs = in_sizes[0] / (256 * 80 * 80);
    const int total_rows = 3 * (80 * 80 + 40 * 40 + 20 * 20);  // 25200

    // scale 0: C=256, 80x80, stride 8
    {
        int M = bs * 6400;
        dim3 g((M + TM - 1) / TM, (NTOT + TN - 1) / TN);
        yolo_scale_kernel<<<g, 256>>>(p0, w0, b0, anchors + 0, out,
                                      256, 6400, 80, 8.f, 0, M, total_rows);
    }
    // scale 1: C=512, 40x40, stride 16
    {
        int M = bs * 1600;
        dim3 g((M + TM - 1) / TM, (NTOT + TN - 1) / TN);
        yolo_scale_kernel<<<g, 256>>>(p1, w1, b1, anchors + 6, out,
                                      512, 1600, 40, 16.f, 3 * 6400, M, total_rows);
    }
    // scale 2: C=1024, 20x20, stride 32
    {
        int M = bs * 400;
        dim3 g((M + TM - 1) / TM, (NTOT + TN - 1) / TN);
        yolo_scale_kernel<<<g, 256>>>(p2, w2, b2, anchors + 12, out,
                                      1024, 400, 20, 32.f, 3 * 6400 + 3 * 1600, M, total_rows);
    }
}

// round 5
// speedup vs baseline: 2.1721x; 2.1721x over previous
#include <cuda_runtime.h>
#include <cuda_bf16.h>
#include <cstdint>

// YOLOv5 detect head on sm_103 via warp-level bf16 HMMA (mma.sync m16n8k16).
// Per scale: D[m,n] = sum_c P[b, c, s]*W[n, c], m=(b,s), fused sigmoid decode.
//
// CTA tile: 128m x 128n, K chunks of 32, double-buffered SMEM, 8 warps (2x4).
// SMEM layout: row stride 20 u32 units (80B); unit swizzle u' = (u + ((row>>1)&12)) & 15
//   -> conflict-free STS.32 and fragment LDS.32.

#define STRIDE_U 20

__device__ __forceinline__ int swz(int row, int u) {
    return row * STRIDE_U + ((u + ((row >> 1) & 12)) & 15);
}

__global__ __launch_bounds__(256, 2)
void yolo_mma_kernel(const float* __restrict__ p,
                     const float* __restrict__ wmat,
                     const float* __restrict__ bias,
                     const float* __restrict__ anc,
                     float* __restrict__ out,
                     int C, int S, int nx, float stride_f,
                     int row_off, int total_rows)
{
    __shared__ uint32_t Asm[2][128 * STRIDE_U];
    __shared__ uint32_t Bsm[2][128 * STRIDE_U];
    __shared__ float bias_s[256];
    __shared__ float anc_s[8];

    const int tid  = threadIdx.x;
    const int lane = tid & 31;
    const int wid  = tid >> 5;
    const int wm   = wid >> 2;        // 0..1  (64 m-rows each)
    const int wn   = wid & 3;         // 0..3  (32 n-cols each)
    const int gid  = lane >> 2;       // 0..7
    const int tig  = lane & 3;        // 0..3

    const int n0 = blockIdx.x << 7;
    const int m0 = blockIdx.y << 7;

    if (tid < 255) bias_s[tid] = bias[tid];
    if (tid < 6)   anc_s[tid]  = anc[tid];

    // ---- A loader mapping: thread -> (pixel tm, unit group tj) ----
    const int tm = tid & 127;
    const int tj = tid >> 7;                 // 0/1 -> units 8*tj .. 8*tj+7
    const int am = m0 + tm;
    const int ab = am / S;
    const int as = am - ab * S;
    const size_t a_base = (size_t)ab * (size_t)C * (size_t)S + (size_t)as;

    // ---- B loader mapping ----
    const int bu = tid & 15;                 // k-pair unit
    const int bn = tid >> 4;                 // 0..15 (n rows bn + 16r)

    const int nk = C >> 5;

    uint32_t aR[8], bR[8];

    float acc[4][4][4];
    #pragma unroll
    for (int mt = 0; mt < 4; mt++)
        #pragma unroll
        for (int nt = 0; nt < 4; nt++)
            #pragma unroll
            for (int e = 0; e < 4; e++) acc[mt][nt][e] = 0.f;

    // ---------- prologue: load k-chunk 0 ----------
    {
        #pragma unroll
        for (int i = 0; i < 8; i++) {
            int u = tj * 8 + i;
            const float* q = p + a_base + (size_t)(2 * u) * (size_t)S;
            __nv_bfloat162 h = __floats2bfloat162_rn(q[0], q[S]);
            aR[i] = *reinterpret_cast<uint32_t*>(&h);
        }
        #pragma unroll
        for (int r = 0; r < 8; r++) {
            int ng = n0 + bn + 16 * r;
            float2 v = make_float2(0.f, 0.f);
            if (ng < 255) v = *reinterpret_cast<const float2*>(wmat + (size_t)ng * C + 2 * bu);
            __nv_bfloat162 h = __floats2bfloat162_rn(v.x, v.y);
            bR[r] = *reinterpret_cast<uint32_t*>(&h);
        }
        #pragma unroll
        for (int i = 0; i < 8; i++) Asm[0][swz(tm, tj * 8 + i)] = aR[i];
        #pragma unroll
        for (int r = 0; r < 8; r++) Bsm[0][swz(bn + 16 * r, bu)] = bR[r];
    }
    __syncthreads();

    // ---------- main loop ----------
    for (int it = 0; it < nk; it++) {
        const int buf = it & 1;
        const bool more = (it + 1 < nk);
        if (more) {
            const int k0 = (it + 1) << 5;
            #pragma unroll
            for (int i = 0; i < 8; i++) {
                int u = tj * 8 + i;
                const float* q = p + a_base + (size_t)(k0 + 2 * u) * (size_t)S;
                __nv_bfloat162 h = __floats2bfloat162_rn(q[0], q[S]);
                aR[i] = *reinterpret_cast<uint32_t*>(&h);
            }
            #pragma unroll
            for (int r = 0; r < 8; r++) {
                int ng = n0 + bn + 16 * r;
                float2 v = make_float2(0.f, 0.f);
                if (ng < 255) v = *reinterpret_cast<const float2*>(wmat + (size_t)ng * C + k0 + 2 * bu);
                __nv_bfloat162 h = __floats2bfloat162_rn(v.x, v.y);
                bR[r] = *reinterpret_cast<uint32_t*>(&h);
            }
        }

        #pragma unroll
        for (int ks = 0; ks < 2; ks++) {
            uint32_t af[4][4], bf[4][2];
            #pragma unroll
            for (int mt = 0; mt < 4; mt++) {
                int r0 = wm * 64 + mt * 16 + gid;
                af[mt][0] = Asm[buf][swz(r0,     ks * 8 + tig)];
                af[mt][1] = Asm[buf][swz(r0 + 8, ks * 8 + tig)];
                af[mt][2] = Asm[buf][swz(r0,     ks * 8 + tig + 4)];
                af[mt][3] = Asm[buf][swz(r0 + 8, ks * 8 + tig + 4)];
            }
            #pragma unroll
            for (int nt = 0; nt < 4; nt++) {
                int c0 = wn * 32 + nt * 8 + gid;
                bf[nt][0] = Bsm[buf][swz(c0, ks * 8 + tig)];
                bf[nt][1] = Bsm[buf][swz(c0, ks * 8 + tig + 4)];
            }
            #pragma unroll
            for (int mt = 0; mt < 4; mt++)
                #pragma unroll
                for (int nt = 0; nt < 4; nt++)
                    asm volatile(
                        "mma.sync.aligned.m16n8k16.row.col.f32.bf16.bf16.f32 "
                        "{%0,%1,%2,%3}, {%4,%5,%6,%7}, {%8,%9}, {%0,%1,%2,%3};"
                        : "+f"(acc[mt][nt][0]), "+f"(acc[mt][nt][1]),
                          "+f"(acc[mt][nt][2]), "+f"(acc[mt][nt][3])
                        : "r"(af[mt][0]), "r"(af[mt][1]), "r"(af[mt][2]), "r"(af[mt][3]),
                          "r"(bf[nt][0]), "r"(bf[nt][1]));
        }

        if (more) {
            const int nb = buf ^ 1;
            #pragma unroll
            for (int i = 0; i < 8; i++) Asm[nb][swz(tm, tj * 8 + i)] = aR[i];
            #pragma unroll
            for (int r = 0; r < 8; r++) Bsm[nb][swz(bn + 16 * r, bu)] = bR[r];
        }
        __syncthreads();
    }

    // ---------- epilogue: bias + sigmoid + decode + scatter ----------
    const float aw[3] = { anc_s[0], anc_s[2], anc_s[4] };
    const float ah[3] = { anc_s[1], anc_s[3], anc_s[5] };
    const size_t sS85 = (size_t)S * 85u;

    #pragma unroll
    for (int mt = 0; mt < 4; mt++) {
        #pragma unroll
        for (int half = 0; half < 2; half++) {
            const int m = m0 + wm * 64 + mt * 16 + gid + half * 8;
            const int b  = m / S;
            const int s  = m - b * S;
            const int yy = s / nx;
            const int xx = s - yy * nx;
            const float fxx = (float)xx - 0.5f;
            const float fyy = (float)yy - 0.5f;
            const size_t base = ((size_t)b * (size_t)total_rows + (size_t)row_off + (size_t)s) * 85u;
            #pragma unroll
            for (int nt = 0; nt < 4; nt++) {
                const int n = n0 + wn * 32 + nt * 8 + 2 * tig;
                #pragma unroll
                for (int e = 0; e < 2; e++) {
                    const int nn = n + e;
                    if (nn >= 255) continue;
                    float v  = acc[mt][nt][half * 2 + e] + bias_s[nn];
                    float sg = 1.f / (1.f + __expf(-v));
                    int a = (nn >= 170) ? 2 : ((nn >= 85) ? 1 : 0);
                    int c = nn - a * 85;
                    float o;
                    if (c == 0)      o = (2.f * sg + fxx) * stride_f;
                    else if (c == 1) o = (2.f * sg + fyy) * stride_f;
                    else if (c == 2) { float t = 2.f * sg; o = t * t * aw[a]; }
                    else if (c == 3) { float t = 2.f * sg; o = t * t * ah[a]; }
                    else             o = sg;
                    out[base + (size_t)a * sS85 + (size_t)c] = o;
                }
            }
        }
    }
}

extern "C" void kernel_launch(void* const* d_in, const int* in_sizes, int n_in,
                              void* d_out, int out_size)
{
    const float* p0 = (const float*)d_in[0];
    const float* p1 = (const float*)d_in[1];
    const float* p2 = (const float*)d_in[2];
    const float* w0 = (const float*)d_in[3];
    const float* b0 = (const float*)d_in[4];
    const float* w1 = (const float*)d_in[5];
    const float* b1 = (const float*)d_in[6];
    const float* w2 = (const float*)d_in[7];
    const float* b2 = (const float*)d_in[8];
    const float* anchors = (const float*)d_in[9];
    float* out = (float*)d_out;

    const int bs = in_sizes[0] / (256 * 80 * 80);
    const int total_rows = 3 * (6400 + 1600 + 400);  // 25200

    // scale 0: C=256, S=6400, 80x80, stride 8
    {
        dim3 g(2, (unsigned)(bs * 6400 / 128));
        yolo_mma_kernel<<<g, 256>>>(p0, w0, b0, anchors + 0, out,
                                    256, 6400, 80, 8.f, 0, total_rows);
    }
    // scale 1: C=512, S=1600, 40x40, stride 16
    {
        dim3 g(2, (unsigned)(bs * 1600 / 128));
        yolo_mma_kernel<<<g, 256>>>(p1, w1, b1, anchors + 6, out,
                                    512, 1600, 40, 16.f, 3 * 6400, total_rows);
    }
    // scale 2: C=1024, S=400, 20x20, stride 32
    {
        dim3 g(2, (unsigned)(bs * 400 / 128));
        yolo_mma_kernel<<<g, 256>>>(p2, w2, b2, anchors + 12, out,
                                    1024, 400, 20, 32.f, 3 * 6400 + 3 * 1600, total_rows);
    }
}

// round 7
// speedup vs baseline: 3.0043x; 1.3831x over previous
#include <cuda_runtime.h>
#include <cuda_bf16.h>
#include <cstdint>

// YOLOv5 detect head, unified single-kernel bf16 HMMA (mma.sync m16n8k16) for all
// three scales. CTA tile 128m x 128n, K chunks of 32, double-buffered SMEM.
// SMEM layout: row = 4 x 16B units (32 bf16), row stride 5 units (80B):
//   r*5 mod 8 is a permutation -> conflict-free STS.128 and ldmatrix, no swizzle math.
// Fragments via ldmatrix.x4 (6 per k16-step, loop-invariant addresses).

#define ROWU 5
#define BUFU (128 * ROWU)
#define BUFBYTES (BUFU * 16)

__device__ __forceinline__ uint32_t smem_u32(const void* p) {
    uint32_t a;
    asm("{ .reg .u64 t; cvta.to.shared.u64 t, %1; cvt.u32.u64 %0, t; }"
        : "=r"(a) : "l"(p));
    return a;
}
__device__ __forceinline__ uint32_t pack2(float a, float b) {
    __nv_bfloat162 h = __floats2bfloat162_rn(a, b);
    return *reinterpret_cast<uint32_t*>(&h);
}

__global__ __launch_bounds__(256, 2)
void yolo_all_kernel(const float* __restrict__ p0, const float* __restrict__ p1,
                     const float* __restrict__ p2,
                     const float* __restrict__ w0, const float* __restrict__ w1,
                     const float* __restrict__ w2,
                     const float* __restrict__ bb0, const float* __restrict__ bb1,
                     const float* __restrict__ bb2,
                     const float* __restrict__ anchors,
                     float* __restrict__ out,
                     int bs, int t2, int t1)
{
    __shared__ uint4 Asm[2][BUFU];
    __shared__ uint4 Bsm[2][BUFU];
    __shared__ float bias_s[256];
    __shared__ float anc_s[8];

    const int tid  = threadIdx.x;
    const int lane = tid & 31;
    const int wid  = tid >> 5;
    const int wm   = wid >> 2;     // 0..1
    const int wn   = wid & 3;      // 0..3
    const int gid  = lane >> 2;    // 0..7
    const int tig  = lane & 3;     // 0..3

    // ---- scale dispatch (scale 2 first: deepest K, fewest blocks) ----
    int bid = blockIdx.x;
    const float *p, *wmat, *bi, *anc;
    int C, S, nx, row_off;
    float strd;
    if (bid < 2 * t2) {
        p = p2; wmat = w2; bi = bb2; anc = anchors + 12;
        C = 1024; S = 400; nx = 20; strd = 32.f; row_off = 24000;
    } else if (bid < 2 * (t2 + t1)) {
        bid -= 2 * t2;
        p = p1; wmat = w1; bi = bb1; anc = anchors + 6;
        C = 512; S = 1600; nx = 40; strd = 16.f; row_off = 19200;
    } else {
        bid -= 2 * (t2 + t1);
        p = p0; wmat = w0; bi = bb0; anc = anchors;
        C = 256; S = 6400; nx = 80; strd = 8.f; row_off = 0;
    }
    const int m0   = (bid >> 1) << 7;
    const int n0   = (bid & 1) << 7;
    const int Mtot = bs * S;

    if (tid < 255) bias_s[tid] = bi[tid];
    if (tid < 6)   anc_s[tid]  = anc[tid];

    // ---- producer mappings ----
    const int arow = tid & 127;
    const int au   = tid >> 7;                 // units au, au+2
    int am = m0 + arow; if (am >= Mtot) am = Mtot - 1;
    const int ab  = am / S;
    const int as_ = am - ab * S;
    const float* abase = p + (size_t)ab * (size_t)C * (size_t)S + (size_t)as_;

    const int brow = tid & 127;
    const int buu  = tid >> 7;
    const int bng  = n0 + brow;
    const float* bbase = (bng < 255) ? (wmat + (size_t)bng * (size_t)C) : nullptr;

    // ---- loop-invariant ldmatrix addresses ----
    const uint32_t a_sm0 = smem_u32(&Asm[0][0]);
    const uint32_t b_sm0 = smem_u32(&Bsm[0][0]);
    const int l8 = lane & 7, lg = lane >> 3;
    uint32_t aAddr[4], bAddr[2];
    #pragma unroll
    for (int mt = 0; mt < 4; mt++)
        aAddr[mt] = a_sm0 + ((((wm * 64 + mt * 16 + (lg & 1) * 8 + l8) * ROWU) + (lg >> 1)) << 4);
    #pragma unroll
    for (int pr = 0; pr < 2; pr++)
        bAddr[pr] = b_sm0 + ((((wn * 32 + pr * 16 + (lg >> 1) * 8 + l8) * ROWU) + (lg & 1)) << 4);

    float acc[4][4][4] = {};
    const int nk = C >> 5;

    auto produce = [&](int k0, int nb) {
        #pragma unroll
        for (int uu = 0; uu < 2; uu++) {
            int u = au + uu * 2;
            const float* q = abase + (size_t)(k0 + u * 8) * (size_t)S;
            uint4 v;
            v.x = pack2(q[0],               q[(size_t)S]);
            v.y = pack2(q[2 * (size_t)S],   q[3 * (size_t)S]);
            v.z = pack2(q[4 * (size_t)S],   q[5 * (size_t)S]);
            v.w = pack2(q[6 * (size_t)S],   q[7 * (size_t)S]);
            Asm[nb][arow * ROWU + u] = v;
        }
        #pragma unroll
        for (int uu = 0; uu < 2; uu++) {
            int u = buu + uu * 2;
            uint4 v = make_uint4(0u, 0u, 0u, 0u);
            if (bbase) {
                float4 x = *reinterpret_cast<const float4*>(bbase + k0 + u * 8);
                float4 y = *reinterpret_cast<const float4*>(bbase + k0 + u * 8 + 4);
                v.x = pack2(x.x, x.y); v.y = pack2(x.z, x.w);
                v.z = pack2(y.x, y.y); v.w = pack2(y.z, y.w);
            }
            Bsm[nb][brow * ROWU + u] = v;
        }
    };

    produce(0, 0);
    __syncthreads();

    for (int it = 0; it < nk; ++it) {
        const int buf = it & 1;
        const uint32_t boff = (uint32_t)buf * BUFBYTES;
        if (it + 1 < nk) produce((it + 1) << 5, buf ^ 1);

        #pragma unroll
        for (int ks = 0; ks < 2; ks++) {
            uint32_t af[4][4], bf[2][4];
            #pragma unroll
            for (int mt = 0; mt < 4; mt++)
                asm volatile("ldmatrix.sync.aligned.m8n8.x4.shared.b16 {%0,%1,%2,%3}, [%4];"
                             : "=r"(af[mt][0]), "=r"(af[mt][1]), "=r"(af[mt][2]), "=r"(af[mt][3])
                             : "r"(aAddr[mt] + boff + ks * 32));
            #pragma unroll
            for (int pr = 0; pr < 2; pr++)
                asm volatile("ldmatrix.sync.aligned.m8n8.x4.shared.b16 {%0,%1,%2,%3}, [%4];"
                             : "=r"(bf[pr][0]), "=r"(bf[pr][1]), "=r"(bf[pr][2]), "=r"(bf[pr][3])
                             : "r"(bAddr[pr] + boff + ks * 32));
            #pragma unroll
            for (int mt = 0; mt < 4; mt++)
                #pragma unroll
                for (int nt = 0; nt < 4; nt++)
                    asm volatile(
                        "mma.sync.aligned.m16n8k16.row.col.f32.bf16.bf16.f32 "
                        "{%0,%1,%2,%3}, {%4,%5,%6,%7}, {%8,%9}, {%0,%1,%2,%3};"
                        : "+f"(acc[mt][nt][0]), "+f"(acc[mt][nt][1]),
                          "+f"(acc[mt][nt][2]), "+f"(acc[mt][nt][3])
                        : "r"(af[mt][0]), "r"(af[mt][1]), "r"(af[mt][2]), "r"(af[mt][3]),
                          "r"(bf[nt >> 1][(nt & 1) * 2]), "r"(bf[nt >> 1][(nt & 1) * 2 + 1]));
        }
        __syncthreads();
    }

    // ---------- epilogue: bias + sigmoid + decode + scatter ----------
    const float aw[3] = { anc_s[0], anc_s[2], anc_s[4] };
    const float ah[3] = { anc_s[1], anc_s[3], anc_s[5] };
    const size_t sS85 = (size_t)S * 85u;
    const int total_rows = 25200;

    #pragma unroll
    for (int mt = 0; mt < 4; mt++) {
        #pragma unroll
        for (int half = 0; half < 2; half++) {
            const int m = m0 + wm * 64 + mt * 16 + gid + half * 8;
            if (m >= Mtot) continue;
            const int b  = m / S;
            const int s  = m - b * S;
            const int yy = s / nx;
            const int xx = s - yy * nx;
            const float fxx = (float)xx - 0.5f;
            const float fyy = (float)yy - 0.5f;
            const size_t base = ((size_t)b * (size_t)total_rows + (size_t)row_off + (size_t)s) * 85u;
            #pragma unroll
            for (int nt = 0; nt < 4; nt++) {
                const int n = n0 + wn * 32 + nt * 8 + 2 * tig;
                #pragma unroll
                for (int e = 0; e < 2; e++) {
                    const int nn = n + e;
                    if (nn >= 255) continue;
                    float v  = acc[mt][nt][half * 2 + e] + bias_s[nn];
                    float sg = 1.f / (1.f + __expf(-v));
                    int a = (nn >= 170) ? 2 : ((nn >= 85) ? 1 : 0);
                    int c = nn - a * 85;
                    float o;
                    if (c == 0)      o = (2.f * sg + fxx) * strd;
                    else if (c == 1) o = (2.f * sg + fyy) * strd;
                    else if (c == 2) { float t = 2.f * sg; o = t * t * aw[a]; }
                    else if (c == 3) { float t = 2.f * sg; o = t * t * ah[a]; }
                    else             o = sg;
                    out[base + (size_t)a * sS85 + (size_t)c] = o;
                }
            }
        }
    }
}

extern "C" void kernel_launch(void* const* d_in, const int* in_sizes, int n_in,
                              void* d_out, int out_size)
{
    const float* p0 = (const float*)d_in[0];
    const float* p1 = (const float*)d_in[1];
    const float* p2 = (const float*)d_in[2];
    const float* w0 = (const float*)d_in[3];
    const float* b0 = (const float*)d_in[4];
    const float* w1 = (const float*)d_in[5];
    const float* b1 = (const float*)d_in[6];
    const float* w2 = (const float*)d_in[7];
    const float* b2 = (const float*)d_in[8];
    const float* anchors = (const float*)d_in[9];
    float* out = (float*)d_out;

    const int bs = in_sizes[0] / (256 * 80 * 80);
    const int t2 = (bs * 400  + 127) / 128;
    const int t1 = (bs * 1600 + 127) / 128;
    const int t0 = (bs * 6400 + 127) / 128;
    const int grid = 2 * (t0 + t1 + t2);

    yolo_all_kernel<<<grid, 256>>>(p0, p1, p2, w0, w1, w2, b0, b1, b2,
                                   anchors, out, bs, t2, t1);
}